// round 8
// baseline (speedup 1.0000x reference)
#include <cuda_runtime.h>

typedef unsigned long long u64;
typedef unsigned int u32;

// ---- packed f32x2 helpers (Blackwell sm_100a) ----
__device__ __forceinline__ u64 pk2(float lo, float hi) {
    u64 r; asm("mov.b64 %0, {%1, %2};" : "=l"(r) : "f"(lo), "f"(hi)); return r;
}
__device__ __forceinline__ void upk2(u64 v, float& lo, float& hi) {
    asm("mov.b64 {%0, %1}, %2;" : "=f"(lo), "=f"(hi) : "l"(v));
}
__device__ __forceinline__ u64 fma2(u64 a, u64 b, u64 c) {
    u64 r; asm("fma.rn.f32x2 %0, %1, %2, %3;" : "=l"(r) : "l"(a), "l"(b), "l"(c)); return r;
}
__device__ __forceinline__ u64 dup2(u32 m) {
    u64 r; asm("mov.b64 %0, {%1, %1};" : "=l"(r) : "r"(m)); return r;
}

// 10-qubit register: wire w = flat-index bit (9-w).
// 1 element per warp; 32 lanes; 32 packed amps per thread.
// XOR-skewed storage: register r (5 bits) holds the amp whose local bits are
//   y = r ^ lane  (all 5 local bits skewed by the 5 lane bits).
// Wire assignment alternates per layer (parity p = d&1):
//   p=0: local slot v <-> global bit v   (wire 9-v); lane slot u <-> bit 5+u (wire 4-u)
//   p=1: local slot v <-> global bit 5+v (wire 4-v); lane slot u <-> bit u   (wire 9-u)
// Swap(lane j <-> local j) in this skew = plain shfl_xor(1<<j) on regs with bit j set.

__global__ __launch_bounds__(128, 4)
void qsim_kernel(const float* __restrict__ x,
                 const float* __restrict__ params,
                 const float* __restrict__ w_cls,
                 const float* __restrict__ b_cls,
                 float* __restrict__ out, int B)
{
    __shared__ float tsh[64], cwork[64], T2[64], wsh[160], bsh[16];
    __shared__ float Cprod_sh;
    const int tid = threadIdx.x;
    if (tid < 60) {
        float s, c;
        sincosf(params[tid] * 0.5f, &s, &c);
        tsh[tid] = s / c;          // tan(theta/2)
        cwork[tid] = c;
    }
    for (int k = tid; k < 160; k += 128) wsh[k] = w_cls[k];
    if (tid < 16) bsh[tid] = b_cls[tid];
    __syncthreads();
    // per-layer gate order: k=0..4 phase-1 slots, k=5..9 phase-2 slots
    if (tid < 60) {
        int d = tid / 10, k = tid % 10, p = d & 1;
        int wire;
        if (k < 5) wire = p ? 4 - k : 9 - k;
        else { int j = k - 5; wire = p ? 9 - j : 4 - j; }
        T2[tid] = tsh[d * 10 + wire];
    }
    if (tid == 0) {
        float pp = 1.0f;
        for (int k = 0; k < 60; k++) pp *= cwork[k];
        Cprod_sh = pp;             // deferred cos product
    }
    __syncthreads();
    const float Cprod = Cprod_sh;

    const int l    = tid & 31;                       // 5-bit lane
    const int elem = blockIdx.x * (blockDim.x >> 5) + (tid >> 5);
    if (elem >= B) return;

    // ---------- initial product state from RX layer (parity 0, skewed) ----------
    float cx[10], sx[10];
#pragma unroll
    for (int q = 0; q < 10; q++) {
        float xv = x[elem * 10 + q];
        sincosf(xv * 0.5f, &sx[q], &cx[q]);
    }
    // lane product: lane slot u <-> bit 5+u <-> wire 4-u
    float lp = Cprod;
#pragma unroll
    for (int u = 0; u < 5; u++)
        lp *= ((l >> u) & 1) ? sx[4 - u] : cx[4 - u];

    // skew-aware per-level factors: reg bit v=1 means amp bit y_v = 1^l_v
    float fhi[5], flo[5];
#pragma unroll
    for (int v = 0; v < 5; v++) {
        const bool lb = (l >> v) & 1;
        fhi[v] = lb ? cx[9 - v] : sx[9 - v];
        flo[v] = lb ? sx[9 - v] : cx[9 - v];
    }

    float pr[32];
    pr[0] = lp;
#pragma unroll
    for (int v = 0; v < 5; v++) {
#pragma unroll
        for (int i = 0; i < 16; i++) {
            if (i < (1 << v)) {
                pr[i | (1 << v)] = pr[i] * fhi[v];
                pr[i]            = pr[i] * flo[v];
            }
        }
    }

    // phase (-i)^popc(b): b-popc = popc(r) + 2*(popc(l) - popc(r&l))
    // per-reg extra sign bit: parity(r&l) ^ parity(l), via 32-bit table
    u32 Tpar = 0;
    if (l & 1)  Tpar ^= 0xAAAAAAAAu;
    if (l & 2)  Tpar ^= 0xCCCCCCCCu;
    if (l & 4)  Tpar ^= 0xF0F0F0F0u;
    if (l & 8)  Tpar ^= 0xFF00FF00u;
    if (l & 16) Tpar ^= 0xFFFF0000u;
    if (__popc(l) & 1) Tpar ^= 0xFFFFFFFFu;

    u64 st[32];
#pragma unroll
    for (int r = 0; r < 32; r++) {
        const int C = __popc(r);                       // compile-time
        const u32 e31 = ((Tpar >> r) & 1u) << 31;
        const u32 bits = __float_as_uint(pr[r]);
        if ((C & 1) == 0) {
            const u32 reb = bits ^ e31 ^ ((u32)((C >> 1) & 1) << 31);
            st[r] = pk2(__uint_as_float(reb), 0.0f);
        } else {
            const u32 imb = bits ^ e31 ^ ((u32)(((C >> 1) & 1) ^ 1) << 31);
            st[r] = pk2(0.0f, __uint_as_float(imb));
        }
    }

    // ---------- CZ flip tables (32-bit words indexed by r) ----------
    // K bit y = ADJ5(y); xor-permute indices by l so bit r = ADJ5(r^l).
    u32 Bw = 0x4748B848u;
    if (l & 1)  Bw = ((Bw & 0x55555555u) << 1) | ((Bw & 0xAAAAAAAAu) >> 1);
    if (l & 2)  Bw = ((Bw & 0x33333333u) << 2) | ((Bw & 0xCCCCCCCCu) >> 2);
    if (l & 4)  Bw = ((Bw & 0x0F0F0F0Fu) << 4) | ((Bw & 0xF0F0F0F0u) >> 4);
    if (l & 8)  Bw = ((Bw & 0x00FF00FFu) << 8) | ((Bw & 0xFF00FF00u) >> 8);
    if (l & 16) Bw = (Bw << 16) | (Bw >> 16);
    const u32 adj5l = (__popc(l & (l >> 1)) & 1) ? 0xFFFFFFFFu : 0u;
    const u32 X0 = (l & 1)  ? 0x55555555u : 0xAAAAAAAAu;   // bit r = y0
    const u32 X4 = (l & 16) ? 0x0000FFFFu : 0xFFFF0000u;   // bit r = y4
    // exit parity 1 (after d=0,2,4): flip = ADJ5(l) ^ (l4 & y0) ^ ADJ5(y)
    const u32 W1 = Bw ^ adj5l ^ ((l & 16) ? X0 : 0u);
    // exit parity 0 (after d=1,3):   flip = ADJ5(y) ^ (y4 & l0) ^ ADJ5(l)
    const u32 W0 = Bw ^ adj5l ^ ((l & 1)  ? X4 : 0u);

    // ---------- 6 variational layers ----------
#pragma unroll 1
    for (int d = 0; d < 6; d++) {

        // phase 1: gate the 5 wires on local slots (skew-signed)
#pragma unroll
        for (int k = 0; k < 5; k++) {
            const float t = T2[d * 10 + k];
            const float te = ((l >> k) & 1) ? -t : t;
            const u64 tt = pk2(te, te), nt = pk2(-te, -te);
#pragma unroll
            for (int w = 0; w < 16; w++) {
                const int i  = ((w >> k) << (k + 1)) | (w & ((1 << k) - 1));
                const int j2 = i | (1 << k);
                const u64 a0 = st[i], a1 = st[j2];
                st[i]  = fma2(nt, a1, a0);   // a0 - te*a1
                st[j2] = fma2(tt, a0, a1);   // a1 + te*a0
            }
        }

        // swaps: lane slot j <-> local slot j  (clean shfl, no fixups)
#pragma unroll
        for (int j = 0; j < 5; j++) {
#pragma unroll
            for (int r = 0; r < 32; r++)
                if (r & (1 << j))
                    st[r] = __shfl_xor_sync(0xffffffffu, st[r], 1 << j);
        }

        // phase 2: gate the 5 wires that just arrived in local slots
#pragma unroll
        for (int k = 0; k < 5; k++) {
            const float t = T2[d * 10 + 5 + k];
            const float te = ((l >> k) & 1) ? -t : t;
            const u64 tt = pk2(te, te), nt = pk2(-te, -te);
#pragma unroll
            for (int w = 0; w < 16; w++) {
                const int i  = ((w >> k) << (k + 1)) | (w & ((1 << k) - 1));
                const int j2 = i | (1 << k);
                const u64 a0 = st[i], a1 = st[j2];
                st[i]  = fma2(nt, a1, a0);
                st[j2] = fma2(tt, a0, a1);
            }
        }

        // CZ chain (diagonal): sign-bit XOR; last layer's CZ skipped
        if (d < 5) {
            const u32 W = (d & 1) ? W0 : W1;   // exit parity = (d&1)^1
#pragma unroll
            for (int r = 0; r < 32; r++) {
                const u32 m = (W << (31 - r)) & 0x80000000u;
                st[r] ^= dup2(m);
            }
        }
    }

    // ---------- probabilities and <Z_q> (final layout = parity 0, skewed) ----------
    float t_all = 0.0f, sb[5] = {0, 0, 0, 0, 0};
#pragma unroll
    for (int r = 0; r < 32; r++) {
        float re, im; upk2(st[r], re, im);
        const float p2 = fmaf(im, im, re * re);
        t_all += p2;
#pragma unroll
        for (int v = 0; v < 5; v++)
            if (r & (1 << v)) sb[v] += p2;
    }
    float ex[10];
#pragma unroll
    for (int q2 = 0; q2 < 5; q2++)                    // lane slots: bit 5+u -> wire 4-u
        ex[q2] = ((l >> (4 - q2)) & 1) ? -t_all : t_all;
#pragma unroll
    for (int v = 0; v < 5; v++) {                     // skewed local slots: bit v -> wire 9-v
        const float e = t_all - 2.0f * sb[v];
        ex[9 - v] = ((l >> v) & 1) ? -e : e;
    }

    // reduce across all 32 lanes of this element
#pragma unroll
    for (int m = 16; m >= 1; m >>= 1) {
#pragma unroll
        for (int q2 = 0; q2 < 10; q2++)
            ex[q2] += __shfl_xor_sync(0xffffffffu, ex[q2], m);
    }

    // ---------- classifier head: lanes 0..15 emit one class each ----------
    if (l < 16) {
        float acc = bsh[l];
#pragma unroll
        for (int q2 = 0; q2 < 10; q2++)
            acc = fmaf(ex[q2], wsh[l * 10 + q2], acc);
        out[elem * 16 + l] = acc;
    }
}

extern "C" void kernel_launch(void* const* d_in, const int* in_sizes, int n_in,
                              void* d_out, int out_size)
{
    const float* x      = (const float*)d_in[0];  // (B, 10)
    const float* params = (const float*)d_in[1];  // (6, 10)
    const float* w_cls  = (const float*)d_in[2];  // (16, 10)
    const float* b_cls  = (const float*)d_in[3];  // (16,)
    float* out = (float*)d_out;

    const int B = in_sizes[0] / 10;
    const int elems_per_block = 4;                // 4 warps x 1 element
    const int blocks = (B + elems_per_block - 1) / elems_per_block;
    qsim_kernel<<<blocks, 128>>>(x, params, w_cls, b_cls, out, B);
}

// round 9
// speedup vs baseline: 1.0773x; 1.0773x over previous
#include <cuda_runtime.h>

typedef unsigned long long u64;
typedef unsigned int u32;

// ---- packed f32x2 helpers (Blackwell sm_100a) ----
__device__ __forceinline__ u64 pk2(float lo, float hi) {
    u64 r; asm("mov.b64 %0, {%1, %2};" : "=l"(r) : "f"(lo), "f"(hi)); return r;
}
__device__ __forceinline__ void upk2(u64 v, float& lo, float& hi) {
    asm("mov.b64 {%0, %1}, %2;" : "=f"(lo), "=f"(hi) : "l"(v));
}
__device__ __forceinline__ u64 fma2(u64 a, u64 b, u64 c) {
    u64 r; asm("fma.rn.f32x2 %0, %1, %2, %3;" : "=l"(r) : "l"(a), "l"(b), "l"(c)); return r;
}
__device__ __forceinline__ u64 dup2(u32 m) {
    u64 r; asm("mov.b64 %0, {%1, %1};" : "=l"(r) : "r"(m)); return r;
}

// 10-qubit register: wire w = flat-index bit (9-w).
// 2 elements per warp; 16 lanes (l = lane&15) per element; 64 amps/thread.
// XOR-skewed storage: register r holds the amp whose local-slot bits are
//   y = r ^ (l & 15)   (bits 0..3 skewed by lane bits; bits 4,5 unskewed)
// Wire assignment alternates per layer (parity p):
//   p=0: lane slot u <-> global bit 6+u ; local slot v <-> global bit v
//   p=1: lane slot u <-> global bit u   ; local slot v<4 <-> bit 6+v ; slots 4,5 <-> bits 4,5
// Swap(lane j <-> local j) in this skew = plain shfl_xor(1<<j) on regs with bit j set.
// Phase-2 gates on slot k commute with swaps on bit j!=k (the swap preserves
// lane bit k, so the gate's lane-dependent sign matches across the exchange),
// which lets swaps and gates interleave for latency hiding.

template<int J>
__device__ __forceinline__ void swap_bit(u64 (&st)[64]) {
#pragma unroll
    for (int r = 0; r < 64; r++)
        if (r & (1 << J))
            st[r] = __shfl_xor_sync(0xffffffffu, st[r], 1 << J);
}

template<int K>
__device__ __forceinline__ void gate_slot(u64 (&st)[64], u64 tt, u64 nt) {
#pragma unroll
    for (int w = 0; w < 32; w++) {
        const int i  = ((w >> K) << (K + 1)) | (w & ((1 << K) - 1));
        const int j2 = i | (1 << K);
        const u64 a0 = st[i], a1 = st[j2];
        st[i]  = fma2(nt, a1, a0);   // a0 - te*a1
        st[j2] = fma2(tt, a0, a1);   // a1 + te*a0
    }
}

__global__ __launch_bounds__(128, 3)
void qsim_kernel(const float* __restrict__ x,
                 const float* __restrict__ params,
                 const float* __restrict__ w_cls,
                 const float* __restrict__ b_cls,
                 float* __restrict__ out, int B)
{
    __shared__ float tsh[64], cwork[64], T2[64], wsh[160], bsh[16];
    __shared__ float Cprod_sh;
    const int tid = threadIdx.x;
    if (tid < 60) {
        float s, c;
        sincosf(params[tid] * 0.5f, &s, &c);
        tsh[tid] = s / c;          // tan(theta/2)
        cwork[tid] = c;
    }
    for (int k = tid; k < 160; k += 128) wsh[k] = w_cls[k];
    if (tid < 16) bsh[tid] = b_cls[tid];
    __syncthreads();
    // reorder thetas into per-layer gate order: k=0..5 phase-1 slots, k=6..9 phase-2 slots
    if (tid < 60) {
        int d = tid / 10, k = tid % 10, p = d & 1;
        int wire;
        if (k < 6) wire = p ? ((k < 4) ? 3 - k : 9 - k) : 9 - k;
        else { int j = k - 6; wire = p ? 9 - j : 3 - j; }
        T2[tid] = tsh[d * 10 + wire];
    }
    if (tid == 0) {
        float pp = 1.0f;
        for (int k = 0; k < 60; k++) pp *= cwork[k];
        Cprod_sh = pp;             // deferred cos product
    }
    __syncthreads();
    const float Cprod = Cprod_sh;

    const int lane = tid & 31;
    const int l    = lane & 15;
    const int half = lane >> 4;
    const int elem = (blockIdx.x * (blockDim.x >> 5) + (tid >> 5)) * 2 + half;
    if (elem >= B) return;

    // ---------- initial product state from RX layer (parity 0, skewed) ----------
    float cx[10], sx[10];
#pragma unroll
    for (int q = 0; q < 10; q++) {
        float xv = x[elem * 10 + q];
        sincosf(xv * 0.5f, &sx[q], &cx[q]);
    }
    // lane product: lane slot u <-> bit 6+u <-> wire 3-u
    float lp = Cprod;
#pragma unroll
    for (int u = 0; u < 4; u++)
        lp *= ((l >> u) & 1) ? sx[3 - u] : cx[3 - u];

    // skew-aware per-level factors: reg bit v=1 means amp bit y_v = 1^l_v (v<4)
    float fhi[6], flo[6];
#pragma unroll
    for (int v = 0; v < 4; v++) {
        const bool lb = (l >> v) & 1;
        fhi[v] = lb ? cx[9 - v] : sx[9 - v];
        flo[v] = lb ? sx[9 - v] : cx[9 - v];
    }
    fhi[4] = sx[5]; flo[4] = cx[5];
    fhi[5] = sx[4]; flo[5] = cx[4];

    float pr[64];
    pr[0] = lp;
#pragma unroll
    for (int v = 0; v < 6; v++) {
#pragma unroll
        for (int i = 0; i < 32; i++) {
            if (i < (1 << v)) {
                pr[i | (1 << v)] = pr[i] * fhi[v];
                pr[i]            = pr[i] * flo[v];
            }
        }
    }

    // phase (-i)^popc(b): parity of popc splits; 2E-term via per-thread bit table
    u32 Tpar = 0;
    if (l & 1) Tpar ^= 0xAAAAu;
    if (l & 2) Tpar ^= 0xCCCCu;
    if (l & 4) Tpar ^= 0xF0F0u;
    if (l & 8) Tpar ^= 0xFF00u;
    if (__popc(l) & 1) Tpar ^= 0xFFFFu;

    u64 st[64];
#pragma unroll
    for (int r = 0; r < 64; r++) {
        const int C = __popc(r);                       // compile-time
        const u32 e31 = ((Tpar >> (r & 15)) & 1u) << 31;
        const u32 bits = __float_as_uint(pr[r]);
        if ((C & 1) == 0) {
            const u32 reb = bits ^ e31 ^ ((u32)((C >> 1) & 1) << 31);
            st[r] = pk2(__uint_as_float(reb), 0.0f);
        } else {
            const u32 imb = bits ^ e31 ^ ((u32)(((C >> 1) & 1) ^ 1) << 31);
            st[r] = pk2(0.0f, __uint_as_float(imb));
        }
    }

    // ---------- CZ flip tables (16-bit words indexed by r&15) ----------
    u32 A = 0xB848u;
    if (l & 1) A = ((A & 0x5555u) << 1) | ((A & 0xAAAAu) >> 1);
    if (l & 2) A = ((A & 0x3333u) << 2) | ((A & 0xCCCCu) >> 2);
    if (l & 4) A = ((A & 0x0F0Fu) << 4) | ((A & 0xF0F0u) >> 4);
    if (l & 8) A = ((A & 0x00FFu) << 8) | ((A & 0xFF00u) >> 8);
    const u32 adjl = (__popc(l & (l >> 1)) & 1) ? 0xFFFFu : 0u;
    const u32 base = A ^ adjl;
    const u32 Y0 = (l & 1) ? 0x5555u : 0xAAAAu;   // r-bits where y0=1
    const u32 Y3 = (l & 8) ? 0x00FFu : 0xFF00u;   // r-bits where y3=1
    const u32 L3 = (l & 8) ? 0xFFFFu : 0u;
    const u32 L0 = (l & 1) ? 0xFFFFu : 0u;
    // parity-1 exit: flip = ADJ4(l) ^ l3*r4 ^ r4*r5 ^ r5*y0 ^ ADJ4(y)
    const u32 W1_00 = base;
    const u32 W1_10 = base ^ L3;
    const u32 W1_01 = base ^ Y0;
    const u32 W1_11 = base ^ L3 ^ 0xFFFFu ^ Y0;
    // parity-0 exit: flip = ADJ4(y) ^ y3*r4 ^ r4*r5 ^ r5*l0 ^ ADJ4(l)
    const u32 W0_00 = base;
    const u32 W0_10 = base ^ Y3;
    const u32 W0_01 = base ^ L0;
    const u32 W0_11 = base ^ Y3 ^ 0xFFFFu ^ L0;

    // ---------- 6 variational layers ----------
#pragma unroll 1
    for (int d = 0; d < 6; d++) {
        const int p = d & 1;

        // phase 1: gate the 6 wires on local slots (slots 0-3 skew-signed)
#pragma unroll
        for (int k = 0; k < 6; k++) {
            const float t = T2[d * 10 + k];
            float te = t;
            if (k < 4) te = ((l >> k) & 1) ? -t : t;
            const u64 tt = pk2(te, te), nt = pk2(-te, -te);
#pragma unroll
            for (int w = 0; w < 32; w++) {
                const int i  = ((w >> k) << (k + 1)) | (w & ((1 << k) - 1));
                const int j2 = i | (1 << k);
                const u64 a0 = st[i], a1 = st[j2];
                st[i]  = fma2(nt, a1, a0);   // a0 - te*a1
                st[j2] = fma2(tt, a0, a1);   // a1 + te*a0
            }
        }

        // phase-2 gate coefficients (lane-sign-adjusted)
        u64 g_tt[4], g_nt[4];
#pragma unroll
        for (int k = 0; k < 4; k++) {
            const float t = T2[d * 10 + 6 + k];
            const float te = ((l >> k) & 1) ? -t : t;
            g_tt[k] = pk2(te, te);
            g_nt[k] = pk2(-te, -te);
        }

        // interleaved swaps + phase-2 gates (commuting pairs):
        // each swap's shuffle latency hides under the previous gate's FMAs.
        swap_bit<0>(st);
        swap_bit<1>(st);
        gate_slot<0>(st, g_tt[0], g_nt[0]);
        swap_bit<2>(st);
        gate_slot<1>(st, g_tt[1], g_nt[1]);
        swap_bit<3>(st);
        gate_slot<2>(st, g_tt[2], g_nt[2]);
        gate_slot<3>(st, g_tt[3], g_nt[3]);

        // CZ chain (diagonal): sign-bit XOR from per-thread tables; skip last
        if (d < 5) {
            const int q = p ^ 1;   // exit parity
            const u32 Wa = q ? W1_00 : W0_00;
            const u32 Wb = q ? W1_10 : W0_10;
            const u32 Wc = q ? W1_01 : W0_01;
            const u32 Wd = q ? W1_11 : W0_11;
#pragma unroll
            for (int r = 0; r < 64; r++) {
                const u32 W = ((r >> 4) & 1) ? (((r >> 5) & 1) ? Wd : Wb)
                                             : (((r >> 5) & 1) ? Wc : Wa);
                const u32 m = (W << (31 - (r & 15))) & 0x80000000u;
                st[r] ^= dup2(m);
            }
        }
    }

    // ---------- probabilities and <Z_q> (final layout = parity 0, skewed) ----------
    float t_all = 0.0f, tb[6] = {0, 0, 0, 0, 0, 0};
#pragma unroll
    for (int r = 0; r < 64; r++) {
        float re, im; upk2(st[r], re, im);
        const float p2 = fmaf(im, im, re * re);
        t_all += p2;
#pragma unroll
        for (int v = 0; v < 6; v++)
            if (r & (1 << v)) tb[v] += p2;
    }
    float ex[10];
#pragma unroll
    for (int q2 = 0; q2 < 4; q2++)                    // lane slots: bit 6+u -> wire 3-u
        ex[q2] = ((l >> (3 - q2)) & 1) ? -t_all : t_all;
#pragma unroll
    for (int v = 0; v < 4; v++) {                     // skewed local slots: bit v -> wire 9-v
        const float e = t_all - 2.0f * tb[v];
        ex[9 - v] = ((l >> v) & 1) ? -e : e;
    }
    ex[5] = t_all - 2.0f * tb[4];                     // bit 4 -> wire 5
    ex[4] = t_all - 2.0f * tb[5];                     // bit 5 -> wire 4

    // reduce across the 16 lanes of this element
#pragma unroll
    for (int m = 8; m >= 1; m >>= 1) {
#pragma unroll
        for (int q2 = 0; q2 < 10; q2++)
            ex[q2] += __shfl_xor_sync(0xffffffffu, ex[q2], m);
    }

    // ---------- classifier head: each of 16 lanes emits one class ----------
    {
        float acc = bsh[l];
#pragma unroll
        for (int q2 = 0; q2 < 10; q2++)
            acc = fmaf(ex[q2], wsh[l * 10 + q2], acc);
        out[elem * 16 + l] = acc;
    }
}

extern "C" void kernel_launch(void* const* d_in, const int* in_sizes, int n_in,
                              void* d_out, int out_size)
{
    const float* x      = (const float*)d_in[0];  // (B, 10)
    const float* params = (const float*)d_in[1];  // (6, 10)
    const float* w_cls  = (const float*)d_in[2];  // (16, 10)
    const float* b_cls  = (const float*)d_in[3];  // (16,)
    float* out = (float*)d_out;

    const int B = in_sizes[0] / 10;
    const int elems_per_block = 8;                // 4 warps x 2 elements
    const int blocks = (B + elems_per_block - 1) / elems_per_block;
    qsim_kernel<<<blocks, 128>>>(x, params, w_cls, b_cls, out, B);
}